// round 7
// baseline (speedup 1.0000x reference)
#include <cuda_runtime.h>
#include <cstdint>

// Problem constants (fixed by setup_inputs)
#define B_     64
#define NO_    1024
#define NI_    1024
#define NBT    8                       // batches per tile
#define NCTAS  512                     // 8192 tiles / 16 tiles per CTA
#define TILES_PER_CTA 16

// RHO_R = exp(-DT/TAU_R) = exp(-0.05)
__device__ __constant__ float kRhoR = 0.95122942450071400910f;

// Persistent kernel, static contiguous scheduling:
//   CTA c owns b-tile (c/64) and j in [16*(c%64), 16*(c%64)+16).
//   => per CTA, all 8 hIsyn read streams and 8 Isyn write streams advance
//      contiguously 4KB/tile (64KB sequential spans) and work is perfectly
//      balanced (exactly 16 tiles per CTA).
// Per tile: front-batch 8 streaming float4 loads (MLP=8), register-cached
// rho/w row, FMA + streaming stores, row reduction, neuron update.
__global__ void __launch_bounds__(256, 4)
hetsyn_cell_kernel(const float* __restrict__ x,      // (B, NI)
                   const float* __restrict__ w,      // (NO, NI)
                   const float* __restrict__ rho,    // (NO, NI)
                   const float* __restrict__ hz,     // (B, NO)
                   const float* __restrict__ hIsyn,  // (B, NO, NI)
                   const float* __restrict__ hIr,    // (B, NO)
                   float* __restrict__ z_out,        // (B, NO)
                   float* __restrict__ Isyn_out,     // (B, NO, NI)
                   float* __restrict__ Ir_out)       // (B, NO)
{
    __shared__ float wsum[8][NBT];

    const int t    = threadIdx.x;       // 0..255
    const int lane = t & 31;
    const int warp = t >> 5;

    const int b0 = (blockIdx.x >> 6) * NBT;         // batch tile (0,8,...,56)
    const int j0 = (blockIdx.x & 63) * TILES_PER_CTA; // first j of chunk

    #pragma unroll 1
    for (int i = 0; i < TILES_PER_CTA; ++i) {
        const int j = j0 + i;
        const size_t row0 = ((size_t)b0 * NO_ + j) * (size_t)NI_;

        // ---- Phase 1: front-batch all 8 streaming loads (MLP=8) ----
        float4 hv[NBT];
        {
            const float4* p = reinterpret_cast<const float4*>(hIsyn + row0) + t;
            #pragma unroll
            for (int bb = 0; bb < NBT; ++bb) {
                hv[bb] = __ldcs(p);
                p += (size_t)NO_ * NI_ / 4;
            }
        }

        // rho/w row: L2-resident (8 MB working set, 126 MB L2)
        const size_t wrow = (size_t)j * NI_;
        const float4 rv = __ldg(reinterpret_cast<const float4*>(rho + wrow) + t);
        const float4 wv = __ldg(reinterpret_cast<const float4*>(w   + wrow) + t);

        // ---- Phase 2: compute, streaming store, partial sums ----
        float psum[NBT];
        {
            float4* q = reinterpret_cast<float4*>(Isyn_out + row0) + t;
            #pragma unroll
            for (int bb = 0; bb < NBT; ++bb) {
                const float4 xv = __ldg(reinterpret_cast<const float4*>(
                    x + (size_t)(b0 + bb) * NI_) + t);

                float4 Is;
                Is.x = fmaf(rv.x, hv[bb].x, wv.x * xv.x);
                Is.y = fmaf(rv.y, hv[bb].y, wv.y * xv.y);
                Is.z = fmaf(rv.z, hv[bb].z, wv.z * xv.z);
                Is.w = fmaf(rv.w, hv[bb].w, wv.w * xv.w);

                __stcs(q, Is);
                q += (size_t)NO_ * NI_ / 4;

                psum[bb] = (Is.x + Is.y) + (Is.z + Is.w);
            }
        }

        // ---- Row-sum reduction per batch ----
        #pragma unroll
        for (int bb = 0; bb < NBT; ++bb) {
            #pragma unroll
            for (int off = 16; off > 0; off >>= 1)
                psum[bb] += __shfl_down_sync(0xFFFFFFFFu, psum[bb], off);
        }

        if (lane == 0) {
            #pragma unroll
            for (int bb = 0; bb < NBT; ++bb) wsum[warp][bb] = psum[bb];
        }
        __syncthreads();

        if (t < NBT) {
            float v_in = 0.0f;
            #pragma unroll
            for (int k = 0; k < 8; ++k) v_in += wsum[k][t];

            const int oidx = (b0 + t) * NO_ + j;
            const float Ir = fmaf(kRhoR, hIr[oidx], hz[oidx]);
            Ir_out[oidx] = Ir;
            // v = v_in - THR*Ir; z = (v - THR >= 0), THR = 1
            z_out[oidx]  = (v_in - Ir - 1.0f >= 0.0f) ? 1.0f : 0.0f;
        }

        __syncthreads();   // protect wsum before next tile overwrites it
    }
}

extern "C" void kernel_launch(void* const* d_in, const int* in_sizes, int n_in,
                              void* d_out, int out_size)
{
    // Input order per setup_inputs: x, w, rho, hz, hIsyn, hIr
    const float* x     = (const float*)d_in[0];
    const float* w     = (const float*)d_in[1];
    const float* rho   = (const float*)d_in[2];
    const float* hz    = (const float*)d_in[3];
    const float* hIsyn = (const float*)d_in[4];
    const float* hIr   = (const float*)d_in[5];

    // Output tuple (z, Isyn, Ir) flattened + concatenated
    float* out    = (float*)d_out;
    float* z_out  = out;
    float* Isyn_o = out + (size_t)B_ * NO_;
    float* Ir_out = out + (size_t)B_ * NO_ + (size_t)B_ * NO_ * NI_;

    dim3 grid(NCTAS);   // 512 persistent CTAs, 16 tiles each (exact)
    dim3 block(256);
    hetsyn_cell_kernel<<<grid, block>>>(x, w, rho, hz, hIsyn, hIr,
                                        z_out, Isyn_o, Ir_out);
}

// round 8
// speedup vs baseline: 1.0673x; 1.0673x over previous
#include <cuda_runtime.h>
#include <cstdint>

// Problem constants (fixed by setup_inputs)
#define B_     64
#define NO_    1024
#define NI_    1024
#define NBT    8                       // batches per tile
#define NTILES (NO_ * (B_ / NBT))      // 8192 work units
#define NCTAS  608                     // 152 SMs x 4 resident CTAs

// RHO_R = exp(-DT/TAU_R) = exp(-0.05)
__device__ __constant__ float kRhoR = 0.95122942450071400910f;

// Persistent kernel: 608 CTAs grid-stride over 8192 (j, b-tile) units.
// Per tile: front-batch 8 streaming float4 loads (MLP=8), register-cached
// rho/w row, FMA + streaming stores, row reduction.
// Epilogue is software-pipelined: tile i's neuron outputs are written during
// tile i+1, with ONE barrier per tile placed right after the 8 streaming
// loads are issued (loads fly through the barrier + reduction).
__global__ void __launch_bounds__(256, 4)
hetsyn_cell_kernel(const float* __restrict__ x,      // (B, NI)
                   const float* __restrict__ w,      // (NO, NI)
                   const float* __restrict__ rho,    // (NO, NI)
                   const float* __restrict__ hz,     // (B, NO)
                   const float* __restrict__ hIsyn,  // (B, NO, NI)
                   const float* __restrict__ hIr,    // (B, NO)
                   float* __restrict__ z_out,        // (B, NO)
                   float* __restrict__ Isyn_out,     // (B, NO, NI)
                   float* __restrict__ Ir_out)       // (B, NO)
{
    __shared__ float wsum[2][8][NBT];   // ping-pong [parity][warp][batch]

    const int t    = threadIdx.x;       // 0..255
    const int lane = t & 31;
    const int warp = t >> 5;

    int prev_tile = -1;                 // tile whose epilogue is pending
    int parity    = 0;

    for (int tile = blockIdx.x; tile < NTILES; tile += NCTAS) {
        const int j  = tile & (NO_ - 1);
        const int b0 = (tile >> 10) * NBT;
        const size_t row0 = ((size_t)b0 * NO_ + j) * (size_t)NI_;

        // ---- Phase 1: front-batch all 8 streaming loads (MLP=8) ----
        float4 hv[NBT];
        {
            const float4* p = reinterpret_cast<const float4*>(hIsyn + row0) + t;
            #pragma unroll
            for (int bb = 0; bb < NBT; ++bb) {
                hv[bb] = __ldcs(p);
                p += (size_t)NO_ * NI_ / 4;
            }
        }

        // Single barrier per tile: publishes prev tile's wsum writes.
        // Streaming loads above are already in flight across it.
        __syncthreads();

        // ---- Deferred epilogue for previous tile ----
        if (prev_tile >= 0 && t < NBT) {
            const int pj  = prev_tile & (NO_ - 1);
            const int pb0 = (prev_tile >> 10) * NBT;
            float v_in = 0.0f;
            #pragma unroll
            for (int k = 0; k < 8; ++k) v_in += wsum[parity ^ 1][k][t];

            const int oidx = (pb0 + t) * NO_ + pj;
            const float Ir = fmaf(kRhoR, hIr[oidx], hz[oidx]);
            Ir_out[oidx] = Ir;
            z_out[oidx]  = (v_in - Ir - 1.0f >= 0.0f) ? 1.0f : 0.0f;
        }

        // rho/w row: L2-resident (8 MB working set)
        const size_t wrow = (size_t)j * NI_;
        const float4 rv = __ldg(reinterpret_cast<const float4*>(rho + wrow) + t);
        const float4 wv = __ldg(reinterpret_cast<const float4*>(w   + wrow) + t);

        // ---- Phase 2: compute, streaming store, partial sums ----
        float psum[NBT];
        {
            float4* q = reinterpret_cast<float4*>(Isyn_out + row0) + t;
            #pragma unroll
            for (int bb = 0; bb < NBT; ++bb) {
                const float4 xv = __ldg(reinterpret_cast<const float4*>(
                    x + (size_t)(b0 + bb) * NI_) + t);

                float4 Is;
                Is.x = fmaf(rv.x, hv[bb].x, wv.x * xv.x);
                Is.y = fmaf(rv.y, hv[bb].y, wv.y * xv.y);
                Is.z = fmaf(rv.z, hv[bb].z, wv.z * xv.z);
                Is.w = fmaf(rv.w, hv[bb].w, wv.w * xv.w);

                __stcs(q, Is);
                q += (size_t)NO_ * NI_ / 4;

                psum[bb] = (Is.x + Is.y) + (Is.z + Is.w);
            }
        }

        // ---- Row-sum reduction per batch ----
        #pragma unroll
        for (int bb = 0; bb < NBT; ++bb) {
            #pragma unroll
            for (int off = 16; off > 0; off >>= 1)
                psum[bb] += __shfl_down_sync(0xFFFFFFFFu, psum[bb], off);
        }

        if (lane == 0) {
            #pragma unroll
            for (int bb = 0; bb < NBT; ++bb) wsum[parity][warp][bb] = psum[bb];
        }

        prev_tile = tile;
        parity ^= 1;
    }

    // ---- Final pending epilogue ----
    __syncthreads();
    if (prev_tile >= 0 && t < NBT) {
        const int pj  = prev_tile & (NO_ - 1);
        const int pb0 = (prev_tile >> 10) * NBT;
        float v_in = 0.0f;
        #pragma unroll
        for (int k = 0; k < 8; ++k) v_in += wsum[parity ^ 1][k][t];

        const int oidx = (pb0 + t) * NO_ + pj;
        const float Ir = fmaf(kRhoR, hIr[oidx], hz[oidx]);
        Ir_out[oidx] = Ir;
        z_out[oidx]  = (v_in - Ir - 1.0f >= 0.0f) ? 1.0f : 0.0f;
    }
}

extern "C" void kernel_launch(void* const* d_in, const int* in_sizes, int n_in,
                              void* d_out, int out_size)
{
    // Input order per setup_inputs: x, w, rho, hz, hIsyn, hIr
    const float* x     = (const float*)d_in[0];
    const float* w     = (const float*)d_in[1];
    const float* rho   = (const float*)d_in[2];
    const float* hz    = (const float*)d_in[3];
    const float* hIsyn = (const float*)d_in[4];
    const float* hIr   = (const float*)d_in[5];

    // Output tuple (z, Isyn, Ir) flattened + concatenated
    float* out    = (float*)d_out;
    float* z_out  = out;
    float* Isyn_o = out + (size_t)B_ * NO_;
    float* Ir_out = out + (size_t)B_ * NO_ + (size_t)B_ * NO_ * NI_;

    dim3 grid(NCTAS);   // persistent: 152 SMs x 4 CTAs
    dim3 block(256);
    hetsyn_cell_kernel<<<grid, block>>>(x, w, rho, hz, hIsyn, hIr,
                                        z_out, Isyn_o, Ir_out);
}

// round 9
// speedup vs baseline: 1.1434x; 1.0713x over previous
#include <cuda_runtime.h>
#include <cstdint>

// Problem constants (fixed by setup_inputs)
#define B_     64
#define NO_    1024
#define NI_    1024
#define NBT    8                       // batches per tile
#define NTILES (NO_ * (B_ / NBT))      // 8192 work units
#define NCTAS  608                     // 152 SMs x 4 resident CTAs

// RHO_R = exp(-DT/TAU_R) = exp(-0.05)
__device__ __constant__ float kRhoR = 0.95122942450071400910f;

// Persistent kernel: 608 CTAs grid-stride over 8192 (j, b-tile) units.
// R6 structure (best profiled: 80.0us, DRAM 77.5%) with ONE barrier per
// tile instead of two: wsum is parity ping-ponged, so the overwrite-protect
// barrier is unnecessary (writer of wsum[p] at tile i+2 is separated from
// tile i's readers by the tile i+1 barrier).
__global__ void __launch_bounds__(256, 4)
hetsyn_cell_kernel(const float* __restrict__ x,      // (B, NI)
                   const float* __restrict__ w,      // (NO, NI)
                   const float* __restrict__ rho,    // (NO, NI)
                   const float* __restrict__ hz,     // (B, NO)
                   const float* __restrict__ hIsyn,  // (B, NO, NI)
                   const float* __restrict__ hIr,    // (B, NO)
                   float* __restrict__ z_out,        // (B, NO)
                   float* __restrict__ Isyn_out,     // (B, NO, NI)
                   float* __restrict__ Ir_out)       // (B, NO)
{
    __shared__ float wsum[2][8][NBT];   // [parity][warp][batch]

    const int t    = threadIdx.x;       // 0..255
    const int lane = t & 31;
    const int warp = t >> 5;

    int parity = 0;

    for (int tile = blockIdx.x; tile < NTILES; tile += NCTAS) {
        const int j  = tile & (NO_ - 1);
        const int b0 = (tile >> 10) * NBT;
        const size_t row0 = ((size_t)b0 * NO_ + j) * (size_t)NI_;

        // ---- Phase 1: front-batch all 8 streaming loads (MLP=8) ----
        float4 hv[NBT];
        {
            const float4* p = reinterpret_cast<const float4*>(hIsyn + row0) + t;
            #pragma unroll
            for (int bb = 0; bb < NBT; ++bb) {
                hv[bb] = __ldcs(p);
                p += (size_t)NO_ * NI_ / 4;
            }
        }

        // rho/w row: L2-resident (8 MB working set)
        const size_t wrow = (size_t)j * NI_;
        const float4 rv = __ldg(reinterpret_cast<const float4*>(rho + wrow) + t);
        const float4 wv = __ldg(reinterpret_cast<const float4*>(w   + wrow) + t);

        // ---- Phase 2: compute, streaming store, partial sums ----
        float psum[NBT];
        {
            float4* q = reinterpret_cast<float4*>(Isyn_out + row0) + t;
            #pragma unroll
            for (int bb = 0; bb < NBT; ++bb) {
                const float4 xv = __ldg(reinterpret_cast<const float4*>(
                    x + (size_t)(b0 + bb) * NI_) + t);

                float4 Is;
                Is.x = fmaf(rv.x, hv[bb].x, wv.x * xv.x);
                Is.y = fmaf(rv.y, hv[bb].y, wv.y * xv.y);
                Is.z = fmaf(rv.z, hv[bb].z, wv.z * xv.z);
                Is.w = fmaf(rv.w, hv[bb].w, wv.w * xv.w);

                __stcs(q, Is);
                q += (size_t)NO_ * NI_ / 4;

                psum[bb] = (Is.x + Is.y) + (Is.z + Is.w);
            }
        }

        // ---- Row-sum reduction per batch ----
        #pragma unroll
        for (int bb = 0; bb < NBT; ++bb) {
            #pragma unroll
            for (int off = 16; off > 0; off >>= 1)
                psum[bb] += __shfl_down_sync(0xFFFFFFFFu, psum[bb], off);
        }

        if (lane == 0) {
            #pragma unroll
            for (int bb = 0; bb < NBT; ++bb) wsum[parity][warp][bb] = psum[bb];
        }
        __syncthreads();   // single barrier per tile

        if (t < NBT) {
            float v_in = 0.0f;
            #pragma unroll
            for (int k = 0; k < 8; ++k) v_in += wsum[parity][k][t];

            const int oidx = (b0 + t) * NO_ + j;
            const float Ir = fmaf(kRhoR, hIr[oidx], hz[oidx]);
            Ir_out[oidx] = Ir;
            // v = v_in - THR*Ir; z = (v - THR >= 0), THR = 1
            z_out[oidx]  = (v_in - Ir - 1.0f >= 0.0f) ? 1.0f : 0.0f;
        }

        parity ^= 1;   // next tile writes the other buffer; no 2nd barrier
    }
}

extern "C" void kernel_launch(void* const* d_in, const int* in_sizes, int n_in,
                              void* d_out, int out_size)
{
    // Input order per setup_inputs: x, w, rho, hz, hIsyn, hIr
    const float* x     = (const float*)d_in[0];
    const float* w     = (const float*)d_in[1];
    const float* rho   = (const float*)d_in[2];
    const float* hz    = (const float*)d_in[3];
    const float* hIsyn = (const float*)d_in[4];
    const float* hIr   = (const float*)d_in[5];

    // Output tuple (z, Isyn, Ir) flattened + concatenated
    float* out    = (float*)d_out;
    float* z_out  = out;
    float* Isyn_o = out + (size_t)B_ * NO_;
    float* Ir_out = out + (size_t)B_ * NO_ + (size_t)B_ * NO_ * NI_;

    dim3 grid(NCTAS);   // persistent: 152 SMs x 4 CTAs
    dim3 block(256);
    hetsyn_cell_kernel<<<grid, block>>>(x, w, rho, hz, hIsyn, hIr,
                                        z_out, Isyn_o, Ir_out);
}